// round 5
// baseline (speedup 1.0000x reference)
#include <cuda_runtime.h>

#define FULLMASK 0xffffffffu

static __device__ __forceinline__ float fixv(float p) {
    return (p == -1.0f) ? 0.0f : p;
}

static __device__ __forceinline__ float tanh_fast(float x) {
    float y;
    asm("tanh.approx.f32 %0, %1;" : "=f"(y) : "f"(x));
    return y;
}

static __device__ __forceinline__ void st_release_cta(int* p, int v) {
    asm volatile("st.release.cta.b32 [%0], %1;" :: "l"(p), "r"(v) : "memory");
}

static __device__ __forceinline__ int ld_acquire_cta(const int* p) {
    int v;
    asm volatile("ld.acquire.cta.b32 %0, [%1];" : "=r"(v) : "l"(p) : "memory");
    return v;
}

// One CTA per batch image, 1024 threads, 4 pixels/thread.
// Thread t owns image row (t>>4), cols [4*(t&15)..+3].
// Warp w owns rows 2w (lanes 0-15) and 2w+1 (lanes 16-31).
//
// Separable stencil with NEIGHBOR-ONLY synchronization: per iteration each
// warp publishes its horizontal 3-sums to smem, releases flags[w], then
// acquire-spins on flags[w-1], flags[w+1] before reading the two vertical
// neighbor h-rows. No __syncthreads in the main loop — warps form a loosely
// coupled wavefront instead of a 32-warp barrier convoy.
__global__ __launch_bounds__(1024, 1)
void prop_kernel(const float* __restrict__ X,
                 const float* __restrict__ pred,
                 const float* __restrict__ w,
                 const float* __restrict__ a,
                 const float* __restrict__ bias,
                 const float* __restrict__ scalar,
                 float* __restrict__ out)
{
    constexpr int NS = 64;          // image side
    constexpr int HH = NS * NS;     // 4096 pixels
    constexpr int SROWS = 66;       // +2 zero halo rows
    constexpr int ITERS = 12;
    constexpr int NWARP = 32;

    __shared__ float Hs[2][SROWS * NS];   // horizontal 3-sums, double buffered
    __shared__ int   flags[NWARP];        // per-warp iteration progress

    const int b    = blockIdx.x;
    const int t    = threadIdx.x;
    const int row  = t >> 4;        // 0..63
    const int cb   = t & 15;        // col block (4 cols each)
    const int wrp  = t >> 5;        // warp id 0..31
    const int lane = t & 31;

    // One-time init: zero halo rows (halo indices 0 and 65) in both buffers,
    // and zero the flags. Single barrier covers visibility.
    if (t < NS) {
        Hs[0][t] = 0.f;            Hs[1][t] = 0.f;
        Hs[0][65 * NS + t] = 0.f;  Hs[1][65 * NS + t] = 0.f;
    }
    if (t < NWARP) flags[t] = 0;

    const float s = scalar[0];
    const int c0 = cb * 4;
    const int gbase = b * HH + row * NS + c0;
    const int pbase = row * NS + c0;

    // Global loads (16B aligned, coalesced)
    float4 p0  = *(const float4*)(pred + gbase);
    float4 x0  = *(const float4*)(X    + gbase);
    float4 w0  = *(const float4*)(w    + pbase);
    float4 a0  = *(const float4*)(a    + pbase);
    float4 bb0 = *(const float4*)(bias + pbase);

    // cs = s*(u_fix + bias + a*X), sw = s*w   (loop-invariant, registers)
    float4 cs0, sw0;
    cs0.x = s * (fixv(p0.x) + bb0.x + a0.x * x0.x);
    cs0.y = s * (fixv(p0.y) + bb0.y + a0.y * x0.y);
    cs0.z = s * (fixv(p0.z) + bb0.z + a0.z * x0.z);
    cs0.w = s * (fixv(p0.w) + bb0.w + a0.w * x0.w);
    sw0.x = s * w0.x;  sw0.y = s * w0.y;  sw0.z = s * w0.z;  sw0.w = s * w0.w;

    // smem indices (halo coords: own row stores at row+1; vertical neighbor
    // h-rows live at halo rows `row` and `row+2` for every thread).
    const int sidx = (row + 1) * NS + c0;
    const int vA   =  row      * NS + c0;
    const int vB   = (row + 2) * NS + c0;

    // flag neighbors (clamped; waiting on own flag is trivially satisfied)
    int* const fUp = &flags[(wrp == 0)         ? 0          : wrp - 1];
    int* const fDn = &flags[(wrp == NWARP - 1) ? NWARP - 1  : wrp + 1];
    int* const fMe = &flags[wrp];

    __syncthreads();    // the only block-wide barrier

    float4 r0 = p0;     // u_0 = pred

    #pragma unroll
    for (int it = 0; it < ITERS; ++it) {
        float* __restrict__ Hc = Hs[it & 1];

        // --- horizontal 3-sum of own row (registers + 2 shuffles) ---
        float aL = __shfl_up_sync  (FULLMASK, r0.w, 1);
        float aR = __shfl_down_sync(FULLMASK, r0.x, 1);
        if (cb == 0)  aL = 0.f;     // image left edge (kills half-warp leak too)
        if (cb == 15) aR = 0.f;     // image right edge

        float4 hx;
        hx.x = aL   + r0.x + r0.y;
        hx.y = r0.x + r0.y + r0.z;
        hx.z = r0.y + r0.z + r0.w;
        hx.w = r0.z + r0.w + aR;

        *(float4*)&Hc[sidx] = hx;

        // publish: all lanes' STS done -> release our flag
        __syncwarp();
        if (lane == 0) st_release_cta(fMe, it + 1);

        // wait for both neighbor warps to have published this iteration
        const int target = it + 1;
        while (ld_acquire_cta(fUp) < target) { }
        while (ld_acquire_cta(fDn) < target) { }

        // both vertical neighbor h-rows from smem
        const float4 hu = *(const float4*)&Hc[vA];
        const float4 hd = *(const float4*)&Hc[vB];

        // u_new = tanh(cs + sw * (h_above + h_self + h_below))
        r0.x = tanh_fast(fmaf(sw0.x, hu.x + hx.x + hd.x, cs0.x));
        r0.y = tanh_fast(fmaf(sw0.y, hu.y + hx.y + hd.y, cs0.y));
        r0.z = tanh_fast(fmaf(sw0.z, hu.z + hx.z + hd.z, cs0.z));
        r0.w = tanh_fast(fmaf(sw0.w, hu.w + hx.w + hd.w, cs0.w));
    }

    *(float4*)(out + gbase) = r0;
}

extern "C" void kernel_launch(void* const* d_in, const int* in_sizes, int n_in,
                              void* d_out, int out_size) {
    const float* X      = (const float*)d_in[0];
    const float* pred   = (const float*)d_in[1];
    const float* w      = (const float*)d_in[2];
    const float* a      = (const float*)d_in[3];
    const float* bias   = (const float*)d_in[4];
    const float* scalar = (const float*)d_in[5];
    float* out = (float*)d_out;

    const int B = in_sizes[0] / 4096;   // batch = 128
    prop_kernel<<<B, 1024>>>(X, pred, w, a, bias, scalar, out);
}

// round 6
// speedup vs baseline: 1.2704x; 1.2704x over previous
#include <cuda_runtime.h>

#define FULLMASK 0xffffffffu

static __device__ __forceinline__ float fixv(float p) {
    return (p == -1.0f) ? 0.0f : p;
}

static __device__ __forceinline__ float tanh_fast(float x) {
    float y;
    asm("tanh.approx.f32 %0, %1;" : "=f"(y) : "f"(x));
    return y;
}

// One CTA per batch image, 1024 threads, 4 pixels/thread in a 2x2 tile.
// Warp w owns image rows 2w and 2w+1; lane j owns cols 2j and 2j+1.
//
// Separable stencil: each thread computes horizontal 3-sums for BOTH of its
// rows (registers + 4 intra-warp shuffles), stores them (2x STS.64), and after
// one barrier loads only the two OUTER halo h-rows (2x LDS.64). Each h-row is
// loaded exactly once block-wide; the inner vertical sums reuse registers.
__global__ __launch_bounds__(1024, 1)
void prop_kernel(const float* __restrict__ X,
                 const float* __restrict__ pred,
                 const float* __restrict__ w,
                 const float* __restrict__ a,
                 const float* __restrict__ bias,
                 const float* __restrict__ scalar,
                 float* __restrict__ out)
{
    constexpr int NS = 64;          // image side
    constexpr int HH = NS * NS;     // 4096 pixels
    constexpr int SROWS = 66;       // +2 zero halo rows
    constexpr int ITERS = 12;

    __shared__ float Hs[2][SROWS * NS];   // horizontal 3-sums, double buffered

    const int b    = blockIdx.x;
    const int t    = threadIdx.x;
    const int wrp  = t >> 5;        // 0..31 -> rows 2w, 2w+1
    const int lane = t & 31;        // -> cols 2j, 2j+1

    // Zero halo rows (halo indices 0 and 65) in both buffers, once.
    if (t < NS) {
        Hs[0][t] = 0.f;            Hs[1][t] = 0.f;
        Hs[0][65 * NS + t] = 0.f;  Hs[1][65 * NS + t] = 0.f;
    }

    const float s = scalar[0];
    const int rT = wrp * 2;             // top row
    const int c  = lane * 2;            // left col
    const int gT = b * HH + rT * NS + c;    // global idx, top row
    const int gB = gT + NS;                 // bottom row
    const int pT = rT * NS + c;             // per-pixel param idx, top
    const int pB = pT + NS;

    // Global loads (8B aligned, each row's warp access is 256B contiguous)
    float2 prT = *(const float2*)(pred + gT);
    float2 prB = *(const float2*)(pred + gB);
    float2 xT  = *(const float2*)(X    + gT);
    float2 xB  = *(const float2*)(X    + gB);
    float2 wT  = *(const float2*)(w    + pT);
    float2 wB  = *(const float2*)(w    + pB);
    float2 aT  = *(const float2*)(a    + pT);
    float2 aB  = *(const float2*)(a    + pB);
    float2 bT  = *(const float2*)(bias + pT);
    float2 bB  = *(const float2*)(bias + pB);

    // cs = s*(u_fix + bias + a*X), sw = s*w  (x,y = top row; z,w = bottom row)
    float4 cs, sw;
    cs.x = s * (fixv(prT.x) + bT.x + aT.x * xT.x);
    cs.y = s * (fixv(prT.y) + bT.y + aT.y * xT.y);
    cs.z = s * (fixv(prB.x) + bB.x + aB.x * xB.x);
    cs.w = s * (fixv(prB.y) + bB.y + aB.y * xB.y);
    sw.x = s * wT.x;  sw.y = s * wT.y;  sw.z = s * wB.x;  sw.w = s * wB.y;

    // smem indices (halo coords: image row r lives at halo row r+1)
    const int stT = (rT + 1) * NS + c;   // own top h-row
    const int stB = (rT + 2) * NS + c;   // own bottom h-row
    const int ldU =  rT      * NS + c;   // halo h-row above (image row 2w-1)
    const int ldD = (rT + 3) * NS + c;   // halo h-row below (image row 2w+2)

    __syncthreads();

    // u_0 = pred (x,y top row; z,w bottom row)
    float4 u = make_float4(prT.x, prT.y, prB.x, prB.y);

    #pragma unroll
    for (int it = 0; it < ITERS; ++it) {
        float* __restrict__ Hc = Hs[it & 1];

        // --- horizontal 3-sums for both owned rows ---
        float sT = u.x + u.y;           // pair sums
        float sB = u.z + u.w;
        float lT = __shfl_up_sync  (FULLMASK, u.y, 1);
        float rTn= __shfl_down_sync(FULLMASK, u.x, 1);
        float lB = __shfl_up_sync  (FULLMASK, u.w, 1);
        float rBn= __shfl_down_sync(FULLMASK, u.z, 1);
        if (lane == 0)  { lT = 0.f; lB = 0.f; }   // image left edge
        if (lane == 31) { rTn = 0.f; rBn = 0.f; } // image right edge

        float hT0 = lT + sT,  hT1 = sT + rTn;     // h[2w][c], h[2w][c+1]
        float hB0 = lB + sB,  hB1 = sB + rBn;     // h[2w+1][c], h[2w+1][c+1]

        *(float2*)&Hc[stT] = make_float2(hT0, hT1);
        *(float2*)&Hc[stB] = make_float2(hB0, hB1);
        __syncthreads();

        // outer halo h-rows (each loaded exactly once block-wide)
        const float2 hU = *(const float2*)&Hc[ldU];
        const float2 hD = *(const float2*)&Hc[ldD];

        // vertical sums share m = h_top + h_bot
        float m0 = hT0 + hB0;
        float m1 = hT1 + hB1;

        u.x = tanh_fast(fmaf(sw.x, hU.x + m0, cs.x));
        u.y = tanh_fast(fmaf(sw.y, hU.y + m1, cs.y));
        u.z = tanh_fast(fmaf(sw.z, m0 + hD.x, cs.z));
        u.w = tanh_fast(fmaf(sw.w, m1 + hD.y, cs.w));
    }

    *(float2*)(out + gT) = make_float2(u.x, u.y);
    *(float2*)(out + gB) = make_float2(u.z, u.w);
}

extern "C" void kernel_launch(void* const* d_in, const int* in_sizes, int n_in,
                              void* d_out, int out_size) {
    const float* X      = (const float*)d_in[0];
    const float* pred   = (const float*)d_in[1];
    const float* w      = (const float*)d_in[2];
    const float* a      = (const float*)d_in[3];
    const float* bias   = (const float*)d_in[4];
    const float* scalar = (const float*)d_in[5];
    float* out = (float*)d_out;

    const int B = in_sizes[0] / 4096;   // batch = 128
    prop_kernel<<<B, 1024>>>(X, pred, w, a, bias, scalar, out);
}